// round 16
// baseline (speedup 1.0000x reference)
#include <cuda_runtime.h>
#include <cuda_fp16.h>
#include <cstdint>

#define N_NODES 50000
#define MAX_E   800000
#define DIM     128
#define DOUT    64

// Scratch (no allocations allowed -> __device__ globals)
__device__ int     g_deg[N_NODES];
__device__ int     g_rowptr[N_NODES + 1];
__device__ int     g_cursor[N_NODES];
__device__ unsigned long long g_blk_desc[256]; // lookback: (flag<<32)|value
__device__ float   g_dinv[N_NODES];
__device__ int     g_esrc[MAX_E];
__device__ __half2 g_xs[(size_t)N_NODES * (DIM / 2)]; // dinv[n] * x[n], fp16
__device__ __half2 g_hs[(size_t)N_NODES * (DIM / 2)]; // dinv[n] * relu(h[n]), fp16
__device__ float   g_agg0[(size_t)N_NODES * DIM];     // Adj @ xs
__device__ float   g_agg2[(size_t)N_NODES * DIM];     // Adj @ hs

// ---------------------------------------------------------------------------
// Histogram over dst
// ---------------------------------------------------------------------------
__global__ void hist_kernel(const int* __restrict__ dst, int E) {
    int e = blockIdx.x * blockDim.x + threadIdx.x;
    if (e < E) atomicAdd(&g_deg[dst[e]], 1);
}

// ---------------------------------------------------------------------------
// Single-pass exclusive scan of g_deg -> g_rowptr, decoupled lookback with a
// WARP-PARALLEL window (32 predecessors per step; worst chain 196/32 = 7 hops).
// Also computes g_dinv. flag: 0 = empty, 1 = aggregate, 2 = inclusive prefix.
// Lanes with idx < 0 synthesize (flag=2, value=0) = "prefix before block 0".
// ---------------------------------------------------------------------------
__global__ void scan_kernel(int N, int E) {
    __shared__ int tmp[256];
    __shared__ int s_prev;
    int t = threadIdx.x;
    int b = blockIdx.x;
    int i = b * 256 + t;
    int v = (i < N) ? g_deg[i] : 0;
    tmp[t] = v;
    __syncthreads();
#pragma unroll
    for (int off = 1; off < 256; off <<= 1) {
        int x = (t >= off) ? tmp[t - off] : 0;
        __syncthreads();
        tmp[t] += x;
        __syncthreads();
    }
    int blockSum = tmp[255];

    if (t < 32) {               // warp 0 does the lookback
        if (t == 0)
            atomicExch(&g_blk_desc[b], (1ULL << 32) | (unsigned)blockSum);
        __syncwarp();

        int running = 0;
        int p = b - 1;
        while (p >= 0) {
            int idx = p - t;                       // lane t reads block p-t
            bool valid = (idx >= 0);
            unsigned long long d;
            unsigned flg;
            do {
                d = valid ? atomicAdd(&g_blk_desc[idx], 0ULL)
                          : (2ULL << 32);          // before block 0: prefix 0
                flg = (unsigned)(d >> 32);
            } while (__any_sync(0xffffffffu, flg == 0u));

            unsigned m2 = __ballot_sync(0xffffffffu, flg == 2u);
            int stop = m2 ? (__ffs(m2) - 1) : 32;  // nearest full prefix
            int take = (t <= stop) ? (int)(d & 0xffffffffULL) : 0;
#pragma unroll
            for (int o = 16; o; o >>= 1)
                take += __shfl_down_sync(0xffffffffu, take, o);
            take = __shfl_sync(0xffffffffu, take, 0);
            running += take;
            if (stop < 32) break;                  // consumed a full prefix
            p -= 32;
        }

        if (t == 0) {
            atomicExch(&g_blk_desc[b],
                       (2ULL << 32) | (unsigned)(running + blockSum));
            s_prev = running;
        }
    }
    __syncthreads();
    int prev = s_prev;

    if (i < N) {
        g_rowptr[i] = prev + tmp[t] - v;           // exclusive scan
        int d = g_deg[i];
        g_dinv[i] = (d > 0) ? rsqrtf((float)d) : 0.0f;
    }
    if (b == 0 && t == 0) g_rowptr[N] = E;
}

// ---------------------------------------------------------------------------
// Fused: fill edge list grouped by dst (src index only) + prescale
// xs[n] = fp16(x[n] * dinv[n]).  Grid covers max(E, N*32) threads.
// ---------------------------------------------------------------------------
__global__ void fill_prescale_kernel(const int* __restrict__ src,
                                     const int* __restrict__ dst,
                                     const float* __restrict__ x,
                                     int E, int N) {
    int i = blockIdx.x * blockDim.x + threadIdx.x;

    if (i < N * 32) {          // prescale: 32 float4-lanes per node
        float s = g_dinv[i >> 5];
        float4 v = ((const float4*)x)[i];
        uint2 u;
        *(__half2*)&u.x = __floats2half2_rn(v.x * s, v.y * s);
        *(__half2*)&u.y = __floats2half2_rn(v.z * s, v.w * s);
        ((uint2*)g_xs)[i] = u;
    }
    if (i < E) {               // fill: one edge per thread
        int d = dst[i];
        int pos = g_rowptr[d] + atomicAdd(&g_cursor[d], 1);
        g_esrc[pos] = src[i];
    }
}

// ---------------------------------------------------------------------------
// Aggregation 2.0: out[n] = sum_{edges e: dst=n} feat[src_e].
// fp16 gather (uint4 = 16B = 8 halves per lane), fp32 accumulate.
// One warp per node; 16 lanes cover a 256B row, so the warp processes TWO
// edges per step (half = lane>>4 selects the edge), x2 unrolled = 4/iter.
// Merge across the two halves with shfl_xor(16); one float4 store per lane.
// ---------------------------------------------------------------------------
__global__ __launch_bounds__(256) void agg_kernel(
    const __half2* __restrict__ feat,
    float* __restrict__ out,
    int N)
{
    int node = blockIdx.x * 8 + (threadIdx.x >> 5);
    int lane = threadIdx.x & 31;
    if (node >= N) return;

    int beg = g_rowptr[node];
    int end = g_rowptr[node + 1];
    int half = lane >> 4;    // which edge of the pair
    int chunk = lane & 15;   // which 16B chunk of the feature row

    float acc[8];
#pragma unroll
    for (int i = 0; i < 8; i++) acc[i] = 0.f;

    const uint4* f = (const uint4*)feat;   // row = 16 x uint4 (256B)

    for (int j = beg; j < end; j += 4) {
        int e0 = j + half;
        int e1 = j + 2 + half;
        bool v0 = e0 < end, v1 = e1 < end;
        int s0 = v0 ? __ldg(g_esrc + e0) : 0;
        int s1 = v1 ? __ldg(g_esrc + e1) : 0;
        if (v0) {
            uint4 u = __ldg(&f[(size_t)s0 * 16 + chunk]);
            float2 a0 = __half22float2(*(__half2*)&u.x);
            float2 a1 = __half22float2(*(__half2*)&u.y);
            float2 a2 = __half22float2(*(__half2*)&u.z);
            float2 a3 = __half22float2(*(__half2*)&u.w);
            acc[0] += a0.x; acc[1] += a0.y; acc[2] += a1.x; acc[3] += a1.y;
            acc[4] += a2.x; acc[5] += a2.y; acc[6] += a3.x; acc[7] += a3.y;
        }
        if (v1) {
            uint4 u = __ldg(&f[(size_t)s1 * 16 + chunk]);
            float2 a0 = __half22float2(*(__half2*)&u.x);
            float2 a1 = __half22float2(*(__half2*)&u.y);
            float2 a2 = __half22float2(*(__half2*)&u.z);
            float2 a3 = __half22float2(*(__half2*)&u.w);
            acc[0] += a0.x; acc[1] += a0.y; acc[2] += a1.x; acc[3] += a1.y;
            acc[4] += a2.x; acc[5] += a2.y; acc[6] += a3.x; acc[7] += a3.y;
        }
    }

    // Merge the two edge-subsets (lanes L and L+16 hold the same features)
#pragma unroll
    for (int i = 0; i < 8; i++)
        acc[i] += __shfl_xor_sync(0xffffffffu, acc[i], 16);

    // Lane writes one float4: features chunk*8 + half*4 .. +4
    float4 w = (half == 0) ? make_float4(acc[0], acc[1], acc[2], acc[3])
                           : make_float4(acc[4], acc[5], acc[6], acc[7]);
    ((float4*)(out + (size_t)node * DIM))[chunk * 2 + half] = w;
}

// ---------------------------------------------------------------------------
// GEMM 1: hs = dinv ⊙ relu((dinv ⊙ agg0) @ W + b)  (fp16 output)
// Block: 256 thr = 8 warps; tile 64 rows x 128 cols; thread: 8 rows x 4 cols.
// ---------------------------------------------------------------------------
__global__ __launch_bounds__(256) void gemm_relu_kernel(
    const float* __restrict__ A,
    const float* __restrict__ W,
    const float* __restrict__ bias,
    __half2* __restrict__ outh,
    int M)
{
    __shared__ float sA[64][DIM];
    int warp = threadIdx.x >> 5;
    int lane = threadIdx.x & 31;
    int rowBase = blockIdx.x * 64;

    // Cooperative load of A tile, scaled by dinv[row]
    for (int i = threadIdx.x; i < 64 * 32; i += 256) {
        int r = i >> 5, c4 = i & 31;
        int gr = rowBase + r;
        float4 v = make_float4(0.f, 0.f, 0.f, 0.f);
        if (gr < M) {
            float s = g_dinv[gr];
            v = ((const float4*)(A + (size_t)gr * DIM))[c4];
            v.x *= s; v.y *= s; v.z *= s; v.w *= s;
        }
        ((float4*)sA[r])[c4] = v;
    }
    __syncthreads();

    int r0 = warp * 8;
    float4 acc[8];
#pragma unroll
    for (int r = 0; r < 8; r++) acc[r] = make_float4(0.f, 0.f, 0.f, 0.f);

#pragma unroll 4
    for (int k = 0; k < DIM; k += 2) {
        float4 w0 = ((const float4*)(W + (size_t)k * DIM))[lane];
        float4 w1 = ((const float4*)(W + (size_t)(k + 1) * DIM))[lane];
#pragma unroll
        for (int r = 0; r < 8; r++) {
            float2 a = *(const float2*)&sA[r0 + r][k];
            acc[r].x += a.x * w0.x; acc[r].y += a.x * w0.y;
            acc[r].z += a.x * w0.z; acc[r].w += a.x * w0.w;
            acc[r].x += a.y * w1.x; acc[r].y += a.y * w1.y;
            acc[r].z += a.y * w1.z; acc[r].w += a.y * w1.w;
        }
    }

    float4 b = ((const float4*)bias)[lane];
#pragma unroll
    for (int r = 0; r < 8; r++) {
        int row = rowBase + r0 + r;
        if (row < M) {
            float s = g_dinv[row];
            float rx = fmaxf(acc[r].x + b.x, 0.f) * s;
            float ry = fmaxf(acc[r].y + b.y, 0.f) * s;
            float rz = fmaxf(acc[r].z + b.z, 0.f) * s;
            float rw = fmaxf(acc[r].w + b.w, 0.f) * s;
            uint2 u;
            *(__half2*)&u.x = __floats2half2_rn(rx, ry);
            *(__half2*)&u.y = __floats2half2_rn(rz, rw);
            ((uint2*)outh)[(size_t)row * 32 + lane] = u;
        }
    }
}

// ---------------------------------------------------------------------------
// GEMM 2: mu = (dinv ⊙ A) @ Wmu + bmu (lanes 0..15),
//         ls = (dinv ⊙ A) @ Wls + bls (lanes 16..31)
// Outputs [M,64] each, concatenated: mu at [0, M*64), logstd after.
// ---------------------------------------------------------------------------
__global__ __launch_bounds__(256) void gemm_out_kernel(
    const float* __restrict__ A,
    const float* __restrict__ Wmu,
    const float* __restrict__ bmu,
    const float* __restrict__ Wls,
    const float* __restrict__ bls,
    float* __restrict__ out,
    int M)
{
    __shared__ float sA[64][DIM];
    int warp = threadIdx.x >> 5;
    int lane = threadIdx.x & 31;
    int rowBase = blockIdx.x * 64;

    for (int i = threadIdx.x; i < 64 * 32; i += 256) {
        int r = i >> 5, c4 = i & 31;
        int gr = rowBase + r;
        float4 v = make_float4(0.f, 0.f, 0.f, 0.f);
        if (gr < M) {
            float s = g_dinv[gr];
            v = ((const float4*)(A + (size_t)gr * DIM))[c4];
            v.x *= s; v.y *= s; v.z *= s; v.w *= s;
        }
        ((float4*)sA[r])[c4] = v;
    }
    __syncthreads();

    const float* Wsel = (lane < 16) ? Wmu : Wls;
    const float* bsel = (lane < 16) ? bmu : bls;
    float* obase = (lane < 16) ? out : out + (size_t)M * DOUT;
    int c = (lane & 15) * 4;

    int r0 = warp * 8;
    float4 acc[8];
#pragma unroll
    for (int r = 0; r < 8; r++) acc[r] = make_float4(0.f, 0.f, 0.f, 0.f);

#pragma unroll 4
    for (int k = 0; k < DIM; k += 2) {
        float4 w0 = *(const float4*)(Wsel + (size_t)k * DOUT + c);
        float4 w1 = *(const float4*)(Wsel + (size_t)(k + 1) * DOUT + c);
#pragma unroll
        for (int r = 0; r < 8; r++) {
            float2 a = *(const float2*)&sA[r0 + r][k];
            acc[r].x += a.x * w0.x; acc[r].y += a.x * w0.y;
            acc[r].z += a.x * w0.z; acc[r].w += a.x * w0.w;
            acc[r].x += a.y * w1.x; acc[r].y += a.y * w1.y;
            acc[r].z += a.y * w1.z; acc[r].w += a.y * w1.w;
        }
    }

    float4 b = *(const float4*)(bsel + c);
#pragma unroll
    for (int r = 0; r < 8; r++) {
        int row = rowBase + r0 + r;
        if (row < M) {
            float4 res;
            res.x = acc[r].x + b.x;
            res.y = acc[r].y + b.y;
            res.z = acc[r].z + b.z;
            res.w = acc[r].w + b.w;
            *(float4*)(obase + (size_t)row * DOUT + c) = res;
        }
    }
}

// ---------------------------------------------------------------------------
// Launch
// ---------------------------------------------------------------------------
extern "C" void kernel_launch(void* const* d_in, const int* in_sizes, int n_in,
                              void* d_out, int out_size) {
    const float* x    = (const float*)d_in[0];   // [N, 128]
    const int*   eidx = (const int*)d_in[1];     // [2, E] int32
    const float* w1   = (const float*)d_in[2];   // [128, 128]
    const float* b1   = (const float*)d_in[3];   // [128]
    const float* w_mu = (const float*)d_in[4];   // [128, 64]
    const float* b_mu = (const float*)d_in[5];   // [64]
    const float* w_ls = (const float*)d_in[6];   // [128, 64]
    const float* b_ls = (const float*)d_in[7];   // [64]
    float* out = (float*)d_out;

    int N = in_sizes[0] / DIM;       // 50000
    int E = in_sizes[1] / 2;         // 800000
    const int* src = eidx;
    const int* dst = eidx + E;

    // Zero histogram, cursors, lookback descriptors
    void *p_deg, *p_cur, *p_desc;
    cudaGetSymbolAddress(&p_deg, g_deg);
    cudaGetSymbolAddress(&p_cur, g_cursor);
    cudaGetSymbolAddress(&p_desc, g_blk_desc);
    cudaMemsetAsync(p_deg, 0, (size_t)N_NODES * sizeof(int));
    cudaMemsetAsync(p_cur, 0, (size_t)N_NODES * sizeof(int));
    cudaMemsetAsync(p_desc, 0, 256 * sizeof(unsigned long long));

    float *agg0, *agg2;
    __half2 *xs, *hs;
    cudaGetSymbolAddress((void**)&agg0, g_agg0);
    cudaGetSymbolAddress((void**)&agg2, g_agg2);
    cudaGetSymbolAddress((void**)&xs, g_xs);
    cudaGetSymbolAddress((void**)&hs, g_hs);

    int eblocks = (E + 255) / 256;
    int nblocks = (N + 255) / 256;   // 196
    int fpgrid  = (N * 32 > E ? N * 32 : E);
    int fpblocks = (fpgrid + 255) / 256;

    // CSR build: 3 kernels (hist, warp-lookback scan + dinv, fill + prescale)
    hist_kernel<<<eblocks, 256>>>(dst, E);                       // launch 1
    scan_kernel<<<nblocks, 256>>>(N, E);                         // launch 2
    fill_prescale_kernel<<<fpblocks, 256>>>(src, dst, x, E, N);  // launch 3

    int ablocks = (N + 7) / 8;       // warp per node
    int gblocks = (N + 63) / 64;

    // Layer 1  (agg = 4th kernel launch -> gets the ncu profile)
    agg_kernel<<<ablocks, 256>>>(xs, agg0, N);                   // launch 4
    gemm_relu_kernel<<<gblocks, 256>>>(agg0, w1, b1, hs, N);     // launch 5

    // Layer 2
    agg_kernel<<<ablocks, 256>>>(hs, agg2, N);                   // launch 6
    gemm_out_kernel<<<gblocks, 256>>>(agg2, w_mu, b_mu, w_ls, b_ls, out, N); // 7
}

// round 17
// speedup vs baseline: 1.0497x; 1.0497x over previous
#include <cuda_runtime.h>
#include <cuda_fp16.h>
#include <cstdint>

#define N_NODES 50000
#define MAX_E   800000
#define DIM     128
#define DOUT    64

// Scratch (no allocations allowed -> __device__ globals)
__device__ int     g_deg[N_NODES];
__device__ int     g_rowptr[N_NODES + 1];
__device__ int     g_cursor[N_NODES];
__device__ unsigned long long g_blk_desc[256]; // lookback: (flag<<32)|value
__device__ float   g_dinv[N_NODES];
__device__ int     g_esrc[MAX_E];
__device__ __half2 g_xs[(size_t)N_NODES * (DIM / 2)]; // dinv[n] * x[n], fp16
__device__ __half2 g_hs[(size_t)N_NODES * (DIM / 2)]; // dinv[n] * relu(h[n]), fp16
__device__ float   g_agg0[(size_t)N_NODES * DIM];     // Adj @ xs
__device__ float   g_agg2[(size_t)N_NODES * DIM];     // Adj @ hs

// ---------------------------------------------------------------------------
// Histogram over dst
// ---------------------------------------------------------------------------
__global__ void hist_kernel(const int* __restrict__ dst, int E) {
    int e = blockIdx.x * blockDim.x + threadIdx.x;
    if (e < E) atomicAdd(&g_deg[dst[e]], 1);
}

// ---------------------------------------------------------------------------
// Single-pass exclusive scan of g_deg -> g_rowptr, decoupled lookback with a
// WARP-PARALLEL window (32 predecessors per step). KEPT from R16 (measured
// ~9us improvement over the serial lookback / 3-phase scan).
// flag: 0 = empty, 1 = aggregate, 2 = inclusive prefix.
// ---------------------------------------------------------------------------
__global__ void scan_kernel(int N, int E) {
    __shared__ int tmp[256];
    __shared__ int s_prev;
    int t = threadIdx.x;
    int b = blockIdx.x;
    int i = b * 256 + t;
    int v = (i < N) ? g_deg[i] : 0;
    tmp[t] = v;
    __syncthreads();
#pragma unroll
    for (int off = 1; off < 256; off <<= 1) {
        int x = (t >= off) ? tmp[t - off] : 0;
        __syncthreads();
        tmp[t] += x;
        __syncthreads();
    }
    int blockSum = tmp[255];

    if (t < 32) {               // warp 0 does the lookback
        if (t == 0)
            atomicExch(&g_blk_desc[b], (1ULL << 32) | (unsigned)blockSum);
        __syncwarp();

        int running = 0;
        int p = b - 1;
        while (p >= 0) {
            int idx = p - t;                       // lane t reads block p-t
            bool valid = (idx >= 0);
            unsigned long long d;
            unsigned flg;
            do {
                d = valid ? atomicAdd(&g_blk_desc[idx], 0ULL)
                          : (2ULL << 32);          // before block 0: prefix 0
                flg = (unsigned)(d >> 32);
            } while (__any_sync(0xffffffffu, flg == 0u));

            unsigned m2 = __ballot_sync(0xffffffffu, flg == 2u);
            int stop = m2 ? (__ffs(m2) - 1) : 32;  // nearest full prefix
            int take = (t <= stop) ? (int)(d & 0xffffffffULL) : 0;
#pragma unroll
            for (int o = 16; o; o >>= 1)
                take += __shfl_down_sync(0xffffffffu, take, o);
            take = __shfl_sync(0xffffffffu, take, 0);
            running += take;
            if (stop < 32) break;                  // consumed a full prefix
            p -= 32;
        }

        if (t == 0) {
            atomicExch(&g_blk_desc[b],
                       (2ULL << 32) | (unsigned)(running + blockSum));
            s_prev = running;
        }
    }
    __syncthreads();
    int prev = s_prev;

    if (i < N) {
        g_rowptr[i] = prev + tmp[t] - v;           // exclusive scan
        int d = g_deg[i];
        g_dinv[i] = (d > 0) ? rsqrtf((float)d) : 0.0f;
    }
    if (b == 0 && t == 0) g_rowptr[N] = E;
}

// ---------------------------------------------------------------------------
// Fused: fill edge list grouped by dst (src index only) + prescale
// xs[n] = fp16(x[n] * dinv[n]).  Grid covers max(E, N*32) threads.
// ---------------------------------------------------------------------------
__global__ void fill_prescale_kernel(const int* __restrict__ src,
                                     const int* __restrict__ dst,
                                     const float* __restrict__ x,
                                     int E, int N) {
    int i = blockIdx.x * blockDim.x + threadIdx.x;

    if (i < N * 32) {          // prescale: 32 float4-lanes per node
        float s = g_dinv[i >> 5];
        float4 v = ((const float4*)x)[i];
        uint2 u;
        *(__half2*)&u.x = __floats2half2_rn(v.x * s, v.y * s);
        *(__half2*)&u.y = __floats2half2_rn(v.z * s, v.w * s);
        ((uint2*)g_xs)[i] = u;
    }
    if (i < E) {               // fill: one edge per thread
        int d = dst[i];
        int pos = g_rowptr[d] + atomicAdd(&g_cursor[d], 1);
        g_esrc[pos] = src[i];
    }
}

// ---------------------------------------------------------------------------
// Aggregation (R13 structure, tuned): out[n] = sum_{dst=n} feat[src_e].
// fp16 gather (uint2 = 8B/lane), fp32 accumulate. One warp per node.
// Changes vs R13 (both from the measured issue/latency co-bound):
//   - 8-deep batched prefetch (8 idx + 8 row loads before any consume, MLP=8)
//   - accumulate via FFMA-imm (rt 1) instead of FADD (rt 2); x1.0 bit-exact
// ---------------------------------------------------------------------------
__global__ __launch_bounds__(256) void agg_kernel(
    const __half2* __restrict__ feat,
    float* __restrict__ out,
    int N)
{
    int node = blockIdx.x * 8 + (threadIdx.x >> 5);
    int lane = threadIdx.x & 31;
    if (node >= N) return;

    int beg = g_rowptr[node];
    int end = g_rowptr[node + 1];

    float4 acc = make_float4(0.f, 0.f, 0.f, 0.f);
    const uint2* f = (const uint2*)feat;  // row = 32 x uint2 (256B)

    int j = beg;
    for (; j + 8 <= end; j += 8) {
        int s[8];
#pragma unroll
        for (int q = 0; q < 8; q++) s[q] = __ldg(g_esrc + j + q);
        uint2 u[8];
#pragma unroll
        for (int q = 0; q < 8; q++) u[q] = __ldg(&f[(size_t)s[q] * 32 + lane]);
#pragma unroll
        for (int q = 0; q < 8; q++) {
            float2 fa = __half22float2(*(__half2*)&u[q].x);
            float2 fb = __half22float2(*(__half2*)&u[q].y);
            acc.x = __fmaf_rn(fa.x, 1.0f, acc.x);
            acc.y = __fmaf_rn(fa.y, 1.0f, acc.y);
            acc.z = __fmaf_rn(fb.x, 1.0f, acc.z);
            acc.w = __fmaf_rn(fb.y, 1.0f, acc.w);
        }
    }
    for (; j + 2 <= end; j += 2) {
        int s0 = __ldg(g_esrc + j);
        int s1 = __ldg(g_esrc + j + 1);
        uint2 u0 = __ldg(&f[(size_t)s0 * 32 + lane]);
        uint2 u1 = __ldg(&f[(size_t)s1 * 32 + lane]);
        float2 a0 = __half22float2(*(__half2*)&u0.x);
        float2 b0 = __half22float2(*(__half2*)&u0.y);
        float2 a1 = __half22float2(*(__half2*)&u1.x);
        float2 b1 = __half22float2(*(__half2*)&u1.y);
        acc.x = __fmaf_rn(a0.x, 1.0f, acc.x);
        acc.y = __fmaf_rn(a0.y, 1.0f, acc.y);
        acc.z = __fmaf_rn(b0.x, 1.0f, acc.z);
        acc.w = __fmaf_rn(b0.y, 1.0f, acc.w);
        acc.x = __fmaf_rn(a1.x, 1.0f, acc.x);
        acc.y = __fmaf_rn(a1.y, 1.0f, acc.y);
        acc.z = __fmaf_rn(b1.x, 1.0f, acc.z);
        acc.w = __fmaf_rn(b1.y, 1.0f, acc.w);
    }
    if (j < end) {
        int s0 = __ldg(g_esrc + j);
        uint2 u = __ldg(&f[(size_t)s0 * 32 + lane]);
        float2 fa = __half22float2(*(__half2*)&u.x);
        float2 fb = __half22float2(*(__half2*)&u.y);
        acc.x = __fmaf_rn(fa.x, 1.0f, acc.x);
        acc.y = __fmaf_rn(fa.y, 1.0f, acc.y);
        acc.z = __fmaf_rn(fb.x, 1.0f, acc.z);
        acc.w = __fmaf_rn(fb.y, 1.0f, acc.w);
    }
    ((float4*)out)[(size_t)node * 32 + lane] = acc;
}

// ---------------------------------------------------------------------------
// GEMM 1: hs = dinv ⊙ relu((dinv ⊙ agg0) @ W + b)  (fp16 output)
// Block: 256 thr = 8 warps; tile 64 rows x 128 cols; thread: 8 rows x 4 cols.
// ---------------------------------------------------------------------------
__global__ __launch_bounds__(256) void gemm_relu_kernel(
    const float* __restrict__ A,
    const float* __restrict__ W,
    const float* __restrict__ bias,
    __half2* __restrict__ outh,
    int M)
{
    __shared__ float sA[64][DIM];
    int warp = threadIdx.x >> 5;
    int lane = threadIdx.x & 31;
    int rowBase = blockIdx.x * 64;

    // Cooperative load of A tile, scaled by dinv[row]
    for (int i = threadIdx.x; i < 64 * 32; i += 256) {
        int r = i >> 5, c4 = i & 31;
        int gr = rowBase + r;
        float4 v = make_float4(0.f, 0.f, 0.f, 0.f);
        if (gr < M) {
            float s = g_dinv[gr];
            v = ((const float4*)(A + (size_t)gr * DIM))[c4];
            v.x *= s; v.y *= s; v.z *= s; v.w *= s;
        }
        ((float4*)sA[r])[c4] = v;
    }
    __syncthreads();

    int r0 = warp * 8;
    float4 acc[8];
#pragma unroll
    for (int r = 0; r < 8; r++) acc[r] = make_float4(0.f, 0.f, 0.f, 0.f);

#pragma unroll 4
    for (int k = 0; k < DIM; k += 2) {
        float4 w0 = ((const float4*)(W + (size_t)k * DIM))[lane];
        float4 w1 = ((const float4*)(W + (size_t)(k + 1) * DIM))[lane];
#pragma unroll
        for (int r = 0; r < 8; r++) {
            float2 a = *(const float2*)&sA[r0 + r][k];
            acc[r].x += a.x * w0.x; acc[r].y += a.x * w0.y;
            acc[r].z += a.x * w0.z; acc[r].w += a.x * w0.w;
            acc[r].x += a.y * w1.x; acc[r].y += a.y * w1.y;
            acc[r].z += a.y * w1.z; acc[r].w += a.y * w1.w;
        }
    }

    float4 b = ((const float4*)bias)[lane];
#pragma unroll
    for (int r = 0; r < 8; r++) {
        int row = rowBase + r0 + r;
        if (row < M) {
            float s = g_dinv[row];
            float rx = fmaxf(acc[r].x + b.x, 0.f) * s;
            float ry = fmaxf(acc[r].y + b.y, 0.f) * s;
            float rz = fmaxf(acc[r].z + b.z, 0.f) * s;
            float rw = fmaxf(acc[r].w + b.w, 0.f) * s;
            uint2 u;
            *(__half2*)&u.x = __floats2half2_rn(rx, ry);
            *(__half2*)&u.y = __floats2half2_rn(rz, rw);
            ((uint2*)outh)[(size_t)row * 32 + lane] = u;
        }
    }
}

// ---------------------------------------------------------------------------
// GEMM 2: mu = (dinv ⊙ A) @ Wmu + bmu (lanes 0..15),
//         ls = (dinv ⊙ A) @ Wls + bls (lanes 16..31)
// Outputs [M,64] each, concatenated: mu at [0, M*64), logstd after.
// ---------------------------------------------------------------------------
__global__ __launch_bounds__(256) void gemm_out_kernel(
    const float* __restrict__ A,
    const float* __restrict__ Wmu,
    const float* __restrict__ bmu,
    const float* __restrict__ Wls,
    const float* __restrict__ bls,
    float* __restrict__ out,
    int M)
{
    __shared__ float sA[64][DIM];
    int warp = threadIdx.x >> 5;
    int lane = threadIdx.x & 31;
    int rowBase = blockIdx.x * 64;

    for (int i = threadIdx.x; i < 64 * 32; i += 256) {
        int r = i >> 5, c4 = i & 31;
        int gr = rowBase + r;
        float4 v = make_float4(0.f, 0.f, 0.f, 0.f);
        if (gr < M) {
            float s = g_dinv[gr];
            v = ((const float4*)(A + (size_t)gr * DIM))[c4];
            v.x *= s; v.y *= s; v.z *= s; v.w *= s;
        }
        ((float4*)sA[r])[c4] = v;
    }
    __syncthreads();

    const float* Wsel = (lane < 16) ? Wmu : Wls;
    const float* bsel = (lane < 16) ? bmu : bls;
    float* obase = (lane < 16) ? out : out + (size_t)M * DOUT;
    int c = (lane & 15) * 4;

    int r0 = warp * 8;
    float4 acc[8];
#pragma unroll
    for (int r = 0; r < 8; r++) acc[r] = make_float4(0.f, 0.f, 0.f, 0.f);

#pragma unroll 4
    for (int k = 0; k < DIM; k += 2) {
        float4 w0 = *(const float4*)(Wsel + (size_t)k * DOUT + c);
        float4 w1 = *(const float4*)(Wsel + (size_t)(k + 1) * DOUT + c);
#pragma unroll
        for (int r = 0; r < 8; r++) {
            float2 a = *(const float2*)&sA[r0 + r][k];
            acc[r].x += a.x * w0.x; acc[r].y += a.x * w0.y;
            acc[r].z += a.x * w0.z; acc[r].w += a.x * w0.w;
            acc[r].x += a.y * w1.x; acc[r].y += a.y * w1.y;
            acc[r].z += a.y * w1.z; acc[r].w += a.y * w1.w;
        }
    }

    float4 b = *(const float4*)(bsel + c);
#pragma unroll
    for (int r = 0; r < 8; r++) {
        int row = rowBase + r0 + r;
        if (row < M) {
            float4 res;
            res.x = acc[r].x + b.x;
            res.y = acc[r].y + b.y;
            res.z = acc[r].z + b.z;
            res.w = acc[r].w + b.w;
            *(float4*)(obase + (size_t)row * DOUT + c) = res;
        }
    }
}

// ---------------------------------------------------------------------------
// Launch
// ---------------------------------------------------------------------------
extern "C" void kernel_launch(void* const* d_in, const int* in_sizes, int n_in,
                              void* d_out, int out_size) {
    const float* x    = (const float*)d_in[0];   // [N, 128]
    const int*   eidx = (const int*)d_in[1];     // [2, E] int32
    const float* w1   = (const float*)d_in[2];   // [128, 128]
    const float* b1   = (const float*)d_in[3];   // [128]
    const float* w_mu = (const float*)d_in[4];   // [128, 64]
    const float* b_mu = (const float*)d_in[5];   // [64]
    const float* w_ls = (const float*)d_in[6];   // [128, 64]
    const float* b_ls = (const float*)d_in[7];   // [64]
    float* out = (float*)d_out;

    int N = in_sizes[0] / DIM;       // 50000
    int E = in_sizes[1] / 2;         // 800000
    const int* src = eidx;
    const int* dst = eidx + E;

    // Zero histogram, cursors, lookback descriptors
    void *p_deg, *p_cur, *p_desc;
    cudaGetSymbolAddress(&p_deg, g_deg);
    cudaGetSymbolAddress(&p_cur, g_cursor);
    cudaGetSymbolAddress(&p_desc, g_blk_desc);
    cudaMemsetAsync(p_deg, 0, (size_t)N_NODES * sizeof(int));
    cudaMemsetAsync(p_cur, 0, (size_t)N_NODES * sizeof(int));
    cudaMemsetAsync(p_desc, 0, 256 * sizeof(unsigned long long));

    float *agg0, *agg2;
    __half2 *xs, *hs;
    cudaGetSymbolAddress((void**)&agg0, g_agg0);
    cudaGetSymbolAddress((void**)&agg2, g_agg2);
    cudaGetSymbolAddress((void**)&xs, g_xs);
    cudaGetSymbolAddress((void**)&hs, g_hs);

    int eblocks = (E + 255) / 256;
    int nblocks = (N + 255) / 256;   // 196
    int fpgrid  = (N * 32 > E ? N * 32 : E);
    int fpblocks = (fpgrid + 255) / 256;

    // CSR build: 3 kernels (hist, warp-lookback scan + dinv, fill + prescale)
    hist_kernel<<<eblocks, 256>>>(dst, E);                       // launch 1
    scan_kernel<<<nblocks, 256>>>(N, E);                         // launch 2
    fill_prescale_kernel<<<fpblocks, 256>>>(src, dst, x, E, N);  // launch 3

    int ablocks = (N + 7) / 8;       // warp per node
    int gblocks = (N + 63) / 64;

    // Layer 1  (agg = 4th kernel launch -> gets the ncu profile)
    agg_kernel<<<ablocks, 256>>>(xs, agg0, N);                   // launch 4
    gemm_relu_kernel<<<gblocks, 256>>>(agg0, w1, b1, hs, N);     // launch 5

    // Layer 2
    agg_kernel<<<ablocks, 256>>>(hs, agg2, N);                   // launch 6
    gemm_out_kernel<<<gblocks, 256>>>(agg2, w_mu, b_mu, w_ls, b_ls, out, N); // 7
}